// round 7
// baseline (speedup 1.0000x reference)
#include <cuda_runtime.h>
#include <cuda_bf16.h>
#include <cstdint>

#define N_DIM 8192
#define M_DIM 16384
#define D_DIM 256

#define BM 128
#define BN 128
#define BK 64
#define KT 4
#define THREADS 256
#define TILES 4                                   // col-tiles per CTA
#define GRID_X (M_DIM / BN / TILES)               // 32
#define GRID_Y (N_DIM / BM)                       // 64
#define TOTAL_CTAS (GRID_X * GRID_Y)              // 2048

#define STAGE_BYTES 32768  // A(16KB) + B(16KB)
#define A_OFF 0
#define B_OFF 16384

#define PRED_PITCH 136     // bf16 elems per row (128 + 8 pad -> conflict-free)
#define PRED_OFF (2 * STAGE_BYTES)                       // 65536
#define PRED_BYTES (BM * PRED_PITCH * 2)                 // 34816
#define SMEM_TOTAL (PRED_OFF + PRED_BYTES)               // 100352

// -------- scratch (no allocations allowed) --------
__device__ __nv_bfloat16 g_u[(size_t)N_DIM * D_DIM];
__device__ __nv_bfloat16 g_i[(size_t)M_DIM * D_DIM];
__device__ double g_acc = 0.0;
__device__ unsigned g_cnt = 0u;

// -------- tiny helpers --------
__device__ __forceinline__ void cp_async16(uint32_t dst, const void* src) {
    asm volatile("cp.async.cg.shared.global [%0], [%1], 16;\n" :: "r"(dst), "l"(src));
}
__device__ __forceinline__ void cp_commit() {
    asm volatile("cp.async.commit_group;\n" ::: "memory");
}
template <int n>
__device__ __forceinline__ void cp_wait() {
    asm volatile("cp.async.wait_group %0;\n" :: "n"(n) : "memory");
}
__device__ __forceinline__ void prefetch_l2(const void* p) {
    asm volatile("prefetch.global.L2 [%0];\n" :: "l"(p));
}
__device__ __forceinline__ void ldsm_x4(uint32_t& r0, uint32_t& r1, uint32_t& r2,
                                        uint32_t& r3, uint32_t addr) {
    asm volatile("ldmatrix.sync.aligned.m8n8.x4.shared.b16 {%0,%1,%2,%3}, [%4];\n"
                 : "=r"(r0), "=r"(r1), "=r"(r2), "=r"(r3)
                 : "r"(addr));
}
__device__ __forceinline__ void mma16816(float c[4],
                                         uint32_t a0, uint32_t a1, uint32_t a2, uint32_t a3,
                                         uint32_t b0, uint32_t b1) {
    asm volatile(
        "mma.sync.aligned.m16n8k16.row.col.f32.bf16.bf16.f32 "
        "{%0,%1,%2,%3},{%4,%5,%6,%7},{%8,%9},{%0,%1,%2,%3};\n"
        : "+f"(c[0]), "+f"(c[1]), "+f"(c[2]), "+f"(c[3])
        : "r"(a0), "r"(a1), "r"(a2), "r"(a3), "r"(b0), "r"(b1));
}

// -------- fused fp32->bf16 convert + lam*sum(||row||), one warp per row --------
__global__ void conv_kernel(const float* __restrict__ u_mat,
                            const float* __restrict__ i_mat) {
    const int lane = threadIdx.x & 31;
    const int wrp = threadIdx.x >> 5;
    const int row = blockIdx.x * 8 + wrp;

    const float* src;
    __nv_bfloat16* dst;
    if (row < N_DIM) {
        src = u_mat + (size_t)row * D_DIM;
        dst = g_u + (size_t)row * D_DIM;
    } else {
        src = i_mat + (size_t)(row - N_DIM) * D_DIM;
        dst = g_i + (size_t)(row - N_DIM) * D_DIM;
    }

    float4 v0 = *(const float4*)(src + lane * 4);
    float4 v1 = *(const float4*)(src + 128 + lane * 4);

    __nv_bfloat162 p0 = {__float2bfloat16(v0.x), __float2bfloat16(v0.y)};
    __nv_bfloat162 p1 = {__float2bfloat16(v0.z), __float2bfloat16(v0.w)};
    __nv_bfloat162 p2 = {__float2bfloat16(v1.x), __float2bfloat16(v1.y)};
    __nv_bfloat162 p3 = {__float2bfloat16(v1.z), __float2bfloat16(v1.w)};
    ((__nv_bfloat162*)(dst))[lane * 2] = p0;
    ((__nv_bfloat162*)(dst))[lane * 2 + 1] = p1;
    ((__nv_bfloat162*)(dst + 128))[lane * 2] = p2;
    ((__nv_bfloat162*)(dst + 128))[lane * 2 + 1] = p3;

    float ss = v0.x * v0.x + v0.y * v0.y + v0.z * v0.z + v0.w * v0.w +
               v1.x * v1.x + v1.y * v1.y + v1.z * v1.z + v1.w * v1.w;
#pragma unroll
    for (int o = 16; o; o >>= 1) ss += __shfl_xor_sync(0xffffffffu, ss, o);

    __shared__ float red[8];
    if (lane == 0) red[wrp] = 0.1f * sqrtf(ss);
    __syncthreads();
    if (threadIdx.x == 0) {
        float s = 0.f;
#pragma unroll
        for (int w = 0; w < 8; ++w) s += red[w];
        atomicAdd(&g_acc, (double)s);
    }
}

// -------- main: persistent 4-tile CTA, epilogue pipelined across tiles --------
__global__ __launch_bounds__(THREADS, 2)
void pmf_main(const float* __restrict__ rating, const float* __restrict__ mask,
              float* __restrict__ out) {
    extern __shared__ char smem[];
    __nv_bfloat16* pred = (__nv_bfloat16*)(smem + PRED_OFF);

    const int tid = threadIdx.x;
    const int lane = tid & 31;
    const int wid = tid >> 5;          // 8 warps
    const int warp_m = wid >> 2;       // 0..1
    const int warp_n = wid & 3;        // 0..3

    const int row0 = blockIdx.y * BM;
    const uint32_t smem_base = (uint32_t)__cvta_generic_to_shared(smem);
    const __nv_bfloat16* Ag = g_u + (size_t)row0 * D_DIM;

    // loader geometry
    const int lrow = tid >> 3;
    const int lch = tid & 7;
    // ldmatrix geometry
    const int q = lane >> 3;
    const int r8 = lane & 7;
    // pred-store geometry
    const int lrow4 = lane >> 2;
    const int lcol2 = (lane & 3) * 2;

    float loss = 0.f;
    int pend_col = -1;                 // col0 of pending epilogue, -1 = none

    for (int t = 0; t < TILES; ++t) {
        const int col0 = (blockIdx.x * TILES + t) * BN;
        const __nv_bfloat16* Bg = g_i + (size_t)col0 * D_DIM;

        float acc[4][4][4];
#pragma unroll
        for (int i = 0; i < 4; ++i)
#pragma unroll
            for (int j = 0; j < 4; ++j)
#pragma unroll
                for (int k = 0; k < 4; ++k) acc[i][j][k] = 0.f;

        auto load_tile = [&](int kt, int s) {
            const uint32_t sa = smem_base + (uint32_t)s * STAGE_BYTES;
#pragma unroll
            for (int it = 0; it < 4; ++it) {
                int row = lrow + it * 32;
                uint32_t d = sa + A_OFF + row * 128 + (uint32_t)((lch ^ (row & 7)) << 4);
                cp_async16(d, Ag + (size_t)row * D_DIM + kt * BK + lch * 8);
            }
#pragma unroll
            for (int it = 0; it < 4; ++it) {
                int row = lrow + it * 32;
                uint32_t d = sa + B_OFF + row * 128 + (uint32_t)((lch ^ (row & 7)) << 4);
                cp_async16(d, Bg + (size_t)row * D_DIM + kt * BK + lch * 8);
            }
            cp_commit();
        };

        load_tile(0, 0);
        // L2-prefetch this tile's rating/mask; consumed one tile later.
        {
            const float* rbase = rating + (size_t)row0 * M_DIM + col0;
            const float* mbase = mask + (size_t)row0 * M_DIM + col0;
#pragma unroll
            for (int i = 0; i < 2; ++i) {
                int idx = tid + i * THREADS;
                int r = idx >> 2;
                int c = (idx & 3) << 5;
                prefetch_l2(rbase + (size_t)r * M_DIM + c);
                prefetch_l2(mbase + (size_t)r * M_DIM + c);
            }
        }

        auto compute_tile = [&](int s) {
            const uint32_t sa = smem_base + (uint32_t)s * STAGE_BYTES;
#pragma unroll
            for (int ks = 0; ks < 4; ++ks) {
                uint32_t a[4][4];
#pragma unroll
                for (int mf = 0; mf < 4; ++mf) {
                    int arow = warp_m * 64 + mf * 16 + (q & 1) * 8 + r8;
                    int ch = ks * 2 + (q >> 1);
                    uint32_t addr = sa + A_OFF + arow * 128 +
                                    (uint32_t)((ch ^ (arow & 7)) << 4);
                    ldsm_x4(a[mf][0], a[mf][1], a[mf][2], a[mf][3], addr);
                }
                uint32_t b[4][2];
#pragma unroll
                for (int nf2 = 0; nf2 < 2; ++nf2) {
                    int brow = warp_n * 32 + nf2 * 16 + (q >> 1) * 8 + r8;
                    int ch = ks * 2 + (q & 1);
                    uint32_t addr = sa + B_OFF + brow * 128 +
                                    (uint32_t)((ch ^ (brow & 7)) << 4);
                    uint32_t r0, r1, r2, r3;
                    ldsm_x4(r0, r1, r2, r3, addr);
                    b[nf2 * 2][0] = r0;
                    b[nf2 * 2][1] = r1;
                    b[nf2 * 2 + 1][0] = r2;
                    b[nf2 * 2 + 1][1] = r3;
                }
#pragma unroll
                for (int mf = 0; mf < 4; ++mf)
#pragma unroll
                    for (int nf = 0; nf < 4; ++nf)
                        mma16816(acc[mf][nf], a[mf][0], a[mf][1], a[mf][2], a[mf][3],
                                 b[nf][0], b[nf][1]);
            }
        };

        // epilogue chunk for PENDING tile: rows [kt*32, kt*32+32)
        auto epi_chunk = [&](int kt) {
            const float* rbase = rating + (size_t)row0 * M_DIM + pend_col;
            const float* mbase = mask + (size_t)row0 * M_DIM + pend_col;
#pragma unroll
            for (int j = 0; j < 4; ++j) {
                int r = kt * 32 + wid * 4 + j;
                const __nv_bfloat162* prow =
                    (const __nv_bfloat162*)(pred + r * PRED_PITCH);
                __nv_bfloat162 p01 = prow[lane * 2];
                __nv_bfloat162 p23 = prow[lane * 2 + 1];
                float4 rv = *(const float4*)(rbase + (size_t)r * M_DIM + lane * 4);
                float4 mv = *(const float4*)(mbase + (size_t)r * M_DIM + lane * 4);
                float2 f01 = __bfloat1622float2(p01);
                float2 f23 = __bfloat1622float2(p23);
                float d0 = rv.x - f01.x;
                float d1 = rv.y - f01.y;
                float d2 = rv.z - f23.x;
                float d3 = rv.w - f23.y;
                loss += d0 * d0 * mv.x;
                loss += d1 * d1 * mv.y;
                loss += d2 * d2 * mv.z;
                loss += d3 * d3 * mv.w;
            }
        };

        // --- mainloop with interleaved pending epilogue ---
#pragma unroll
        for (int kt = 0; kt < KT; ++kt) {
            if (kt + 1 < KT) {
                load_tile(kt + 1, (kt + 1) & 1);
                cp_wait<1>();
            } else {
                cp_wait<0>();
            }
            __syncthreads();
            compute_tile(kt & 1);
            if (pend_col >= 0) epi_chunk(kt);
            __syncthreads();
        }

        // --- dump accumulators to bf16 pred smem ---
#pragma unroll
        for (int mf = 0; mf < 4; ++mf) {
            int r = warp_m * 64 + mf * 16 + lrow4;
#pragma unroll
            for (int nf = 0; nf < 4; ++nf) {
                int c = warp_n * 32 + nf * 8 + lcol2;
                *(__nv_bfloat162*)(pred + r * PRED_PITCH + c) =
                    __nv_bfloat162{__float2bfloat16(acc[mf][nf][0]),
                                   __float2bfloat16(acc[mf][nf][1])};
                *(__nv_bfloat162*)(pred + (r + 8) * PRED_PITCH + c) =
                    __nv_bfloat162{__float2bfloat16(acc[mf][nf][2]),
                                   __float2bfloat16(acc[mf][nf][3])};
            }
        }
        pend_col = col0;
        // next iteration's first __syncthreads orders these stores before reads
    }

    // --- final exposed epilogue for the last tile ---
    __syncthreads();
#pragma unroll
    for (int kt = 0; kt < KT; ++kt) {
        const float* rbase = rating + (size_t)row0 * M_DIM + pend_col;
        const float* mbase = mask + (size_t)row0 * M_DIM + pend_col;
#pragma unroll
        for (int j = 0; j < 4; ++j) {
            int r = kt * 32 + wid * 4 + j;
            const __nv_bfloat162* prow = (const __nv_bfloat162*)(pred + r * PRED_PITCH);
            __nv_bfloat162 p01 = prow[lane * 2];
            __nv_bfloat162 p23 = prow[lane * 2 + 1];
            float4 rv = *(const float4*)(rbase + (size_t)r * M_DIM + lane * 4);
            float4 mv = *(const float4*)(mbase + (size_t)r * M_DIM + lane * 4);
            float2 f01 = __bfloat1622float2(p01);
            float2 f23 = __bfloat1622float2(p23);
            float d0 = rv.x - f01.x;
            float d1 = rv.y - f01.y;
            float d2 = rv.z - f23.x;
            float d3 = rv.w - f23.y;
            loss += d0 * d0 * mv.x;
            loss += d1 * d1 * mv.y;
            loss += d2 * d2 * mv.z;
            loss += d3 * d3 * mv.w;
        }
    }

    // --- reduce + folded finalize ---
#pragma unroll
    for (int o = 16; o; o >>= 1) loss += __shfl_xor_sync(0xffffffffu, loss, o);
    __shared__ float red[8];
    if (lane == 0) red[wid] = loss;
    __syncthreads();
    if (tid == 0) {
        float s = 0.f;
#pragma unroll
        for (int w = 0; w < 8; ++w) s += red[w];
        atomicAdd(&g_acc, (double)s);
        __threadfence();
        unsigned done = atomicAdd(&g_cnt, 1u);
        if (done == TOTAL_CTAS - 1) {
            out[0] = (float)(*(volatile double*)&g_acc);
            *(volatile double*)&g_acc = 0.0;
            *(volatile unsigned*)&g_cnt = 0u;
        }
    }
}

extern "C" void kernel_launch(void* const* d_in, const int* in_sizes, int n_in,
                              void* d_out, int out_size) {
    const float* rating = (const float*)d_in[0];
    const float* u_mat = (const float*)d_in[1];
    const float* i_mat = (const float*)d_in[2];
    const float* mask = (const float*)d_in[3];
    float* out = (float*)d_out;

    cudaFuncSetAttribute(pmf_main, cudaFuncAttributeMaxDynamicSharedMemorySize,
                         SMEM_TOTAL);

    conv_kernel<<<(N_DIM + M_DIM) / 8, 256>>>(u_mat, i_mat);

    dim3 grid(GRID_X, GRID_Y);  // 32 x 64 = 2048 CTAs, 4 tiles each
    pmf_main<<<grid, THREADS, SMEM_TOTAL>>>(rating, mask, out);
}

// round 8
// speedup vs baseline: 1.4135x; 1.4135x over previous
#include <cuda_runtime.h>
#include <cuda_bf16.h>
#include <cstdint>

#define N_DIM 8192
#define M_DIM 16384
#define D_DIM 256

#define BM 128
#define BN 128
#define BK 64
#define KT 4
#define THREADS 256
#define TOTAL_CTAS ((N_DIM / BM) * (M_DIM / BN))   // 8192

#define STAGE_BYTES 32768  // A(16KB) + B(16KB)
#define A_OFF 0
#define B_OFF 16384

#define PRED_PITCH 136     // bf16 elems per row (128 + 8 pad -> conflict-free)
#define PRED_BYTES (BM * PRED_PITCH * 2)            // 34816 (overlays stage smem)
#define SMEM_TOTAL (2 * STAGE_BYTES)                // 65536 >= PRED_BYTES

// -------- scratch (no allocations allowed) --------
__device__ __nv_bfloat16 g_u[(size_t)N_DIM * D_DIM];
__device__ __nv_bfloat16 g_i[(size_t)M_DIM * D_DIM];
__device__ double g_acc = 0.0;
__device__ unsigned g_cnt = 0u;

// -------- tiny helpers --------
__device__ __forceinline__ void cp_async16(uint32_t dst, const void* src) {
    asm volatile("cp.async.cg.shared.global [%0], [%1], 16;\n" :: "r"(dst), "l"(src));
}
__device__ __forceinline__ void cp_commit() {
    asm volatile("cp.async.commit_group;\n" ::: "memory");
}
template <int n>
__device__ __forceinline__ void cp_wait() {
    asm volatile("cp.async.wait_group %0;\n" :: "n"(n) : "memory");
}
__device__ __forceinline__ void prefetch_l2(const void* p) {
    asm volatile("prefetch.global.L2 [%0];\n" :: "l"(p));
}
__device__ __forceinline__ void ldsm_x4(uint32_t& r0, uint32_t& r1, uint32_t& r2,
                                        uint32_t& r3, uint32_t addr) {
    asm volatile("ldmatrix.sync.aligned.m8n8.x4.shared.b16 {%0,%1,%2,%3}, [%4];\n"
                 : "=r"(r0), "=r"(r1), "=r"(r2), "=r"(r3)
                 : "r"(addr));
}
__device__ __forceinline__ void mma16816(float c[4],
                                         uint32_t a0, uint32_t a1, uint32_t a2, uint32_t a3,
                                         uint32_t b0, uint32_t b1) {
    asm volatile(
        "mma.sync.aligned.m16n8k16.row.col.f32.bf16.bf16.f32 "
        "{%0,%1,%2,%3},{%4,%5,%6,%7},{%8,%9},{%0,%1,%2,%3};\n"
        : "+f"(c[0]), "+f"(c[1]), "+f"(c[2]), "+f"(c[3])
        : "r"(a0), "r"(a1), "r"(a2), "r"(a3), "r"(b0), "r"(b1));
}

// -------- fused fp32->bf16 convert + lam*sum(||row||), one warp per row --------
__global__ void conv_kernel(const float* __restrict__ u_mat,
                            const float* __restrict__ i_mat) {
    const int lane = threadIdx.x & 31;
    const int wrp = threadIdx.x >> 5;
    const int row = blockIdx.x * 8 + wrp;

    const float* src;
    __nv_bfloat16* dst;
    if (row < N_DIM) {
        src = u_mat + (size_t)row * D_DIM;
        dst = g_u + (size_t)row * D_DIM;
    } else {
        src = i_mat + (size_t)(row - N_DIM) * D_DIM;
        dst = g_i + (size_t)(row - N_DIM) * D_DIM;
    }

    float4 v0 = *(const float4*)(src + lane * 4);
    float4 v1 = *(const float4*)(src + 128 + lane * 4);

    __nv_bfloat162 p0 = {__float2bfloat16(v0.x), __float2bfloat16(v0.y)};
    __nv_bfloat162 p1 = {__float2bfloat16(v0.z), __float2bfloat16(v0.w)};
    __nv_bfloat162 p2 = {__float2bfloat16(v1.x), __float2bfloat16(v1.y)};
    __nv_bfloat162 p3 = {__float2bfloat16(v1.z), __float2bfloat16(v1.w)};
    ((__nv_bfloat162*)(dst))[lane * 2] = p0;
    ((__nv_bfloat162*)(dst))[lane * 2 + 1] = p1;
    ((__nv_bfloat162*)(dst + 128))[lane * 2] = p2;
    ((__nv_bfloat162*)(dst + 128))[lane * 2 + 1] = p3;

    float ss = v0.x * v0.x + v0.y * v0.y + v0.z * v0.z + v0.w * v0.w +
               v1.x * v1.x + v1.y * v1.y + v1.z * v1.z + v1.w * v1.w;
#pragma unroll
    for (int o = 16; o; o >>= 1) ss += __shfl_xor_sync(0xffffffffu, ss, o);

    __shared__ float red[8];
    if (lane == 0) red[wrp] = 0.1f * sqrtf(ss);
    __syncthreads();
    if (threadIdx.x == 0) {
        float s = 0.f;
#pragma unroll
        for (int w = 0; w < 8; ++w) s += red[w];
        atomicAdd(&g_acc, (double)s);
    }
}

// -------- main fused GEMM + masked-SSE (+ folded finalize + self-reset) --------
__global__ __launch_bounds__(THREADS, 2)
void pmf_main(const float* __restrict__ rating, const float* __restrict__ mask,
              float* __restrict__ out) {
    extern __shared__ char smem[];
    __nv_bfloat16* pred = (__nv_bfloat16*)smem;   // overlays stages after mainloop
    const int tid = threadIdx.x;
    const int lane = tid & 31;
    const int wid = tid >> 5;          // 8 warps
    const int warp_m = wid >> 2;       // 0..1  (64-row strip)
    const int warp_n = wid & 3;        // 0..3  (32-col strip)

    const int row0 = blockIdx.y * BM;  // u rows
    const int col0 = blockIdx.x * BN;  // i rows

    const uint32_t smem_base = (uint32_t)__cvta_generic_to_shared(smem);
    const __nv_bfloat16* Ag = g_u + (size_t)row0 * D_DIM;
    const __nv_bfloat16* Bg = g_i + (size_t)col0 * D_DIM;

    float acc[4][4][4];
#pragma unroll
    for (int i = 0; i < 4; ++i)
#pragma unroll
        for (int j = 0; j < 4; ++j)
#pragma unroll
            for (int k = 0; k < 4; ++k) acc[i][j][k] = 0.f;

    // --- loader geometry: 16B chunks, 128B rows, xor-swizzled ---
    const int lrow = tid >> 3;  // 0..31
    const int lch = tid & 7;

    auto load_tile = [&](int kt, int s) {
        const uint32_t sa = smem_base + (uint32_t)s * STAGE_BYTES;
#pragma unroll
        for (int it = 0; it < 4; ++it) {
            int row = lrow + it * 32;
            uint32_t d = sa + A_OFF + row * 128 + (uint32_t)((lch ^ (row & 7)) << 4);
            cp_async16(d, Ag + (size_t)row * D_DIM + kt * BK + lch * 8);
        }
#pragma unroll
        for (int it = 0; it < 4; ++it) {
            int row = lrow + it * 32;
            uint32_t d = sa + B_OFF + row * 128 + (uint32_t)((lch ^ (row & 7)) << 4);
            cp_async16(d, Bg + (size_t)row * D_DIM + kt * BK + lch * 8);
        }
        cp_commit();
    };

    // Kick GEMM pipeline, then L2-prefetch this CTA's rating/mask tile so the
    // DRAM stream overlaps the MMA mainloop (short distance — proven in R5).
    load_tile(0, 0);
    {
        const float* rbase = rating + (size_t)row0 * M_DIM + col0;
        const float* mbase = mask + (size_t)row0 * M_DIM + col0;
#pragma unroll
        for (int i = 0; i < 2; ++i) {
            int idx = tid + i * THREADS;      // 0..511
            int r = idx >> 2;
            int c = (idx & 3) << 5;
            prefetch_l2(rbase + (size_t)r * M_DIM + c);
            prefetch_l2(mbase + (size_t)r * M_DIM + c);
        }
    }

    // --- ldmatrix lane geometry ---
    const int q = lane >> 3;
    const int r8 = lane & 7;

    auto compute_tile = [&](int s) {
        const uint32_t sa = smem_base + (uint32_t)s * STAGE_BYTES;
#pragma unroll
        for (int ks = 0; ks < 4; ++ks) {
            uint32_t a[4][4];
#pragma unroll
            for (int mf = 0; mf < 4; ++mf) {
                int arow = warp_m * 64 + mf * 16 + (q & 1) * 8 + r8;
                int ch = ks * 2 + (q >> 1);
                uint32_t addr = sa + A_OFF + arow * 128 +
                                (uint32_t)((ch ^ (arow & 7)) << 4);
                ldsm_x4(a[mf][0], a[mf][1], a[mf][2], a[mf][3], addr);
            }
            uint32_t b[4][2];
#pragma unroll
            for (int nf2 = 0; nf2 < 2; ++nf2) {
                int brow = warp_n * 32 + nf2 * 16 + (q >> 1) * 8 + r8;
                int ch = ks * 2 + (q & 1);
                uint32_t addr = sa + B_OFF + brow * 128 +
                                (uint32_t)((ch ^ (brow & 7)) << 4);
                uint32_t r0, r1, r2, r3;
                ldsm_x4(r0, r1, r2, r3, addr);
                b[nf2 * 2][0] = r0;
                b[nf2 * 2][1] = r1;
                b[nf2 * 2 + 1][0] = r2;
                b[nf2 * 2 + 1][1] = r3;
            }
#pragma unroll
            for (int mf = 0; mf < 4; ++mf)
#pragma unroll
                for (int nf = 0; nf < 4; ++nf)
                    mma16816(acc[mf][nf], a[mf][0], a[mf][1], a[mf][2], a[mf][3],
                             b[nf][0], b[nf][1]);
        }
    };

    // --- 2-stage pipelined mainloop over D ---
#pragma unroll
    for (int kt = 0; kt < KT; ++kt) {
        if (kt + 1 < KT) {
            load_tile(kt + 1, (kt + 1) & 1);
            cp_wait<1>();
        } else {
            cp_wait<0>();
        }
        __syncthreads();
        compute_tile(kt & 1);
        __syncthreads();
    }

    // --- write pred tile into smem as bf16 (fragment layout -> row-major) ---
    {
        const int lrow4 = lane >> 2;
        const int lcol2 = (lane & 3) * 2;
#pragma unroll
        for (int mf = 0; mf < 4; ++mf) {
            int r = warp_m * 64 + mf * 16 + lrow4;
#pragma unroll
            for (int nf = 0; nf < 4; ++nf) {
                int c = warp_n * 32 + nf * 8 + lcol2;
                *(__nv_bfloat162*)(pred + r * PRED_PITCH + c) =
                    __nv_bfloat162{__float2bfloat16(acc[mf][nf][0]),
                                   __float2bfloat16(acc[mf][nf][1])};
                *(__nv_bfloat162*)(pred + (r + 8) * PRED_PITCH + c) =
                    __nv_bfloat162{__float2bfloat16(acc[mf][nf][2]),
                                   __float2bfloat16(acc[mf][nf][3])};
            }
        }
    }
    __syncthreads();

    // --- epilogue: coalesced rating/mask stream, batched loads (MLP~8),
    //     4 independent accumulators to break the FFMA chain ---
    float loss0 = 0.f, loss1 = 0.f, loss2 = 0.f, loss3 = 0.f;
    {
        const float* rbase = rating + (size_t)row0 * M_DIM + col0;
        const float* mbase = mask + (size_t)row0 * M_DIM + col0;
#pragma unroll
        for (int jb = 0; jb < 16; jb += 4) {
            float4 rv[4], mv[4];
#pragma unroll
            for (int j = 0; j < 4; ++j) {
                int r = wid * 16 + jb + j;
                rv[j] = *(const float4*)(rbase + (size_t)r * M_DIM + lane * 4);
                mv[j] = *(const float4*)(mbase + (size_t)r * M_DIM + lane * 4);
            }
#pragma unroll
            for (int j = 0; j < 4; ++j) {
                int r = wid * 16 + jb + j;
                const __nv_bfloat162* prow =
                    (const __nv_bfloat162*)(pred + r * PRED_PITCH);
                __nv_bfloat162 p01 = prow[lane * 2];
                __nv_bfloat162 p23 = prow[lane * 2 + 1];
                float2 f01 = __bfloat1622float2(p01);
                float2 f23 = __bfloat1622float2(p23);
                float d0 = rv[j].x - f01.x;
                float d1 = rv[j].y - f01.y;
                float d2 = rv[j].z - f23.x;
                float d3 = rv[j].w - f23.y;
                loss0 += d0 * d0 * mv[j].x;
                loss1 += d1 * d1 * mv[j].y;
                loss2 += d2 * d2 * mv[j].z;
                loss3 += d3 * d3 * mv[j].w;
            }
        }
    }
    float loss = (loss0 + loss1) + (loss2 + loss3);
#pragma unroll
    for (int o = 16; o; o >>= 1) loss += __shfl_xor_sync(0xffffffffu, loss, o);
    __shared__ float red[8];
    if (lane == 0) red[wid] = loss;
    __syncthreads();
    if (tid == 0) {
        float s = 0.f;
#pragma unroll
        for (int w = 0; w < 8; ++w) s += red[w];
        atomicAdd(&g_acc, (double)s);
        __threadfence();
        unsigned done = atomicAdd(&g_cnt, 1u);
        if (done == TOTAL_CTAS - 1) {
            // last CTA: publish result, then reset accumulators for next replay
            out[0] = (float)(*(volatile double*)&g_acc);
            *(volatile double*)&g_acc = 0.0;
            *(volatile unsigned*)&g_cnt = 0u;
        }
    }
}

extern "C" void kernel_launch(void* const* d_in, const int* in_sizes, int n_in,
                              void* d_out, int out_size) {
    const float* rating = (const float*)d_in[0];
    const float* u_mat = (const float*)d_in[1];
    const float* i_mat = (const float*)d_in[2];
    const float* mask = (const float*)d_in[3];
    float* out = (float*)d_out;

    cudaFuncSetAttribute(pmf_main, cudaFuncAttributeMaxDynamicSharedMemorySize,
                         SMEM_TOTAL);

    conv_kernel<<<(N_DIM + M_DIM) / 8, 256>>>(u_mat, i_mat);

    dim3 grid(M_DIM / BN, N_DIM / BM);  // 128 x 64 = 8192 CTAs
    pmf_main<<<grid, THREADS, SMEM_TOTAL>>>(rating, mask, out);
}

// round 9
// speedup vs baseline: 1.4338x; 1.0144x over previous
#include <cuda_runtime.h>
#include <cuda_bf16.h>
#include <cstdint>

#define N_DIM 8192
#define M_DIM 16384
#define D_DIM 256

#define BM 128
#define BN 128
#define BK 64
#define KT 4
#define THREADS 256
#define TOTAL_CTAS ((N_DIM / BM) * (M_DIM / BN))   // 8192

#define STAGE_BYTES 32768  // A(16KB) + B(16KB)
#define A_OFF 0
#define B_OFF 16384

#define PRED_PITCH 136     // bf16 elems per row (128 + 8 pad -> conflict-free)
#define PRED_BYTES (BM * PRED_PITCH * 2)            // 34816 (overlays stage smem)
#define SMEM_TOTAL (2 * STAGE_BYTES)                // 65536 >= PRED_BYTES

// -------- scratch (no allocations allowed) --------
__device__ __nv_bfloat16 g_u[(size_t)N_DIM * D_DIM];
__device__ __nv_bfloat16 g_i[(size_t)M_DIM * D_DIM];
__device__ double g_acc = 0.0;
__device__ unsigned g_cnt = 0u;

// -------- tiny helpers --------
__device__ __forceinline__ void cp_async16(uint32_t dst, const void* src) {
    asm volatile("cp.async.cg.shared.global [%0], [%1], 16;\n" :: "r"(dst), "l"(src));
}
__device__ __forceinline__ void cp_commit() {
    asm volatile("cp.async.commit_group;\n" ::: "memory");
}
template <int n>
__device__ __forceinline__ void cp_wait() {
    asm volatile("cp.async.wait_group %0;\n" :: "n"(n) : "memory");
}
__device__ __forceinline__ void prefetch_l2(const void* p) {
    asm volatile("prefetch.global.L2 [%0];\n" :: "l"(p));
}
__device__ __forceinline__ void ldsm_x4(uint32_t& r0, uint32_t& r1, uint32_t& r2,
                                        uint32_t& r3, uint32_t addr) {
    asm volatile("ldmatrix.sync.aligned.m8n8.x4.shared.b16 {%0,%1,%2,%3}, [%4];\n"
                 : "=r"(r0), "=r"(r1), "=r"(r2), "=r"(r3)
                 : "r"(addr));
}
__device__ __forceinline__ void mma16816(float c[4],
                                         uint32_t a0, uint32_t a1, uint32_t a2, uint32_t a3,
                                         uint32_t b0, uint32_t b1) {
    asm volatile(
        "mma.sync.aligned.m16n8k16.row.col.f32.bf16.bf16.f32 "
        "{%0,%1,%2,%3},{%4,%5,%6,%7},{%8,%9},{%0,%1,%2,%3};\n"
        : "+f"(c[0]), "+f"(c[1]), "+f"(c[2]), "+f"(c[3])
        : "r"(a0), "r"(a1), "r"(a2), "r"(a3), "r"(b0), "r"(b1));
}

// -------- fused fp32->bf16 convert + lam*sum(||row||), one warp per row --------
__global__ void conv_kernel(const float* __restrict__ u_mat,
                            const float* __restrict__ i_mat) {
    const int lane = threadIdx.x & 31;
    const int wrp = threadIdx.x >> 5;
    const int row = blockIdx.x * 8 + wrp;

    const float* src;
    __nv_bfloat16* dst;
    if (row < N_DIM) {
        src = u_mat + (size_t)row * D_DIM;
        dst = g_u + (size_t)row * D_DIM;
    } else {
        src = i_mat + (size_t)(row - N_DIM) * D_DIM;
        dst = g_i + (size_t)(row - N_DIM) * D_DIM;
    }

    float4 v0 = *(const float4*)(src + lane * 4);
    float4 v1 = *(const float4*)(src + 128 + lane * 4);

    __nv_bfloat162 p0 = {__float2bfloat16(v0.x), __float2bfloat16(v0.y)};
    __nv_bfloat162 p1 = {__float2bfloat16(v0.z), __float2bfloat16(v0.w)};
    __nv_bfloat162 p2 = {__float2bfloat16(v1.x), __float2bfloat16(v1.y)};
    __nv_bfloat162 p3 = {__float2bfloat16(v1.z), __float2bfloat16(v1.w)};
    ((__nv_bfloat162*)(dst))[lane * 2] = p0;
    ((__nv_bfloat162*)(dst))[lane * 2 + 1] = p1;
    ((__nv_bfloat162*)(dst + 128))[lane * 2] = p2;
    ((__nv_bfloat162*)(dst + 128))[lane * 2 + 1] = p3;

    float ss = v0.x * v0.x + v0.y * v0.y + v0.z * v0.z + v0.w * v0.w +
               v1.x * v1.x + v1.y * v1.y + v1.z * v1.z + v1.w * v1.w;
#pragma unroll
    for (int o = 16; o; o >>= 1) ss += __shfl_xor_sync(0xffffffffu, ss, o);

    __shared__ float red[8];
    if (lane == 0) red[wrp] = 0.1f * sqrtf(ss);
    __syncthreads();
    if (threadIdx.x == 0) {
        float s = 0.f;
#pragma unroll
        for (int w = 0; w < 8; ++w) s += red[w];
        atomicAdd(&g_acc, (double)s);
    }
}

// -------- main fused GEMM + masked-SSE (+ folded finalize + self-reset) --------
__global__ __launch_bounds__(THREADS, 2)
void pmf_main(const float* __restrict__ rating, const float* __restrict__ mask,
              float* __restrict__ out) {
    extern __shared__ char smem[];
    __nv_bfloat16* pred = (__nv_bfloat16*)smem;   // overlays stages after mainloop
    const int tid = threadIdx.x;
    const int lane = tid & 31;
    const int wid = tid >> 5;          // 8 warps
    const int warp_m = wid >> 2;       // 0..1  (64-row strip)
    const int warp_n = wid & 3;        // 0..3  (32-col strip)

    const int row0 = blockIdx.y * BM;  // u rows
    const int col0 = blockIdx.x * BN;  // i rows

    const uint32_t smem_base = (uint32_t)__cvta_generic_to_shared(smem);
    const __nv_bfloat16* Ag = g_u + (size_t)row0 * D_DIM;
    const __nv_bfloat16* Bg = g_i + (size_t)col0 * D_DIM;

    float acc[4][4][4];
#pragma unroll
    for (int i = 0; i < 4; ++i)
#pragma unroll
        for (int j = 0; j < 4; ++j)
#pragma unroll
            for (int k = 0; k < 4; ++k) acc[i][j][k] = 0.f;

    // --- loader geometry: 16B chunks, 128B rows, xor-swizzled ---
    const int lrow = tid >> 3;  // 0..31
    const int lch = tid & 7;

    auto load_tile = [&](int kt, int s) {
        const uint32_t sa = smem_base + (uint32_t)s * STAGE_BYTES;
#pragma unroll
        for (int it = 0; it < 4; ++it) {
            int row = lrow + it * 32;
            uint32_t d = sa + A_OFF + row * 128 + (uint32_t)((lch ^ (row & 7)) << 4);
            cp_async16(d, Ag + (size_t)row * D_DIM + kt * BK + lch * 8);
        }
#pragma unroll
        for (int it = 0; it < 4; ++it) {
            int row = lrow + it * 32;
            uint32_t d = sa + B_OFF + row * 128 + (uint32_t)((lch ^ (row & 7)) << 4);
            cp_async16(d, Bg + (size_t)row * D_DIM + kt * BK + lch * 8);
        }
        cp_commit();
    };

    // Kick stage 0, then L2-prefetch this CTA's rating/mask tile so the DRAM
    // stream overlaps the MMA mainloop (short distance — proven in R5/R8).
    load_tile(0, 0);
    {
        const float* rbase = rating + (size_t)row0 * M_DIM + col0;
        const float* mbase = mask + (size_t)row0 * M_DIM + col0;
#pragma unroll
        for (int i = 0; i < 2; ++i) {
            int idx = tid + i * THREADS;      // 0..511
            int r = idx >> 2;
            int c = (idx & 3) << 5;
            prefetch_l2(rbase + (size_t)r * M_DIM + c);
            prefetch_l2(mbase + (size_t)r * M_DIM + c);
        }
    }

    // --- ldmatrix lane geometry ---
    const int q = lane >> 3;
    const int r8 = lane & 7;

    auto compute_tile = [&](int s) {
        const uint32_t sa = smem_base + (uint32_t)s * STAGE_BYTES;
#pragma unroll
        for (int ks = 0; ks < 4; ++ks) {
            uint32_t a[4][4];
#pragma unroll
            for (int mf = 0; mf < 4; ++mf) {
                int arow = warp_m * 64 + mf * 16 + (q & 1) * 8 + r8;
                int ch = ks * 2 + (q >> 1);
                uint32_t addr = sa + A_OFF + arow * 128 +
                                (uint32_t)((ch ^ (arow & 7)) << 4);
                ldsm_x4(a[mf][0], a[mf][1], a[mf][2], a[mf][3], addr);
            }
            uint32_t b[4][2];
#pragma unroll
            for (int nf2 = 0; nf2 < 2; ++nf2) {
                int brow = warp_n * 32 + nf2 * 16 + (q >> 1) * 8 + r8;
                int ch = ks * 2 + (q & 1);
                uint32_t addr = sa + B_OFF + brow * 128 +
                                (uint32_t)((ch ^ (brow & 7)) << 4);
                uint32_t r0, r1, r2, r3;
                ldsm_x4(r0, r1, r2, r3, addr);
                b[nf2 * 2][0] = r0;
                b[nf2 * 2][1] = r1;
                b[nf2 * 2 + 1][0] = r2;
                b[nf2 * 2 + 1][1] = r3;
            }
#pragma unroll
            for (int mf = 0; mf < 4; ++mf)
#pragma unroll
                for (int nf = 0; nf < 4; ++nf)
                    mma16816(acc[mf][nf], a[mf][0], a[mf][1], a[mf][2], a[mf][3],
                             b[nf][0], b[nf][1]);
        }
    };

    // --- single-barrier pipelined mainloop (wait -> BAR -> load next -> MMA) ---
    // Loads are issued AFTER the barrier, so the stage they overwrite (used by
    // compute(kt-1)) is provably drained by that same barrier.
#pragma unroll
    for (int kt = 0; kt < KT; ++kt) {
        cp_wait<0>();
        __syncthreads();
        if (kt + 1 < KT) load_tile(kt + 1, (kt + 1) & 1);
        compute_tile(kt & 1);
    }

    // --- write pred tile into smem as bf16 (fragment layout -> row-major) ---
    __syncthreads();   // drain compute(3) readers before overlaying stage smem
    {
        const int lrow4 = lane >> 2;
        const int lcol2 = (lane & 3) * 2;
#pragma unroll
        for (int mf = 0; mf < 4; ++mf) {
            int r = warp_m * 64 + mf * 16 + lrow4;
#pragma unroll
            for (int nf = 0; nf < 4; ++nf) {
                int c = warp_n * 32 + nf * 8 + lcol2;
                *(__nv_bfloat162*)(pred + r * PRED_PITCH + c) =
                    __nv_bfloat162{__float2bfloat16(acc[mf][nf][0]),
                                   __float2bfloat16(acc[mf][nf][1])};
                *(__nv_bfloat162*)(pred + (r + 8) * PRED_PITCH + c) =
                    __nv_bfloat162{__float2bfloat16(acc[mf][nf][2]),
                                   __float2bfloat16(acc[mf][nf][3])};
            }
        }
    }
    __syncthreads();

    // --- epilogue: coalesced rating/mask stream, batch-8 loads (MLP~16),
    //     4 independent accumulators to break the FFMA chain ---
    float loss0 = 0.f, loss1 = 0.f, loss2 = 0.f, loss3 = 0.f;
    {
        const float* rbase = rating + (size_t)row0 * M_DIM + col0;
        const float* mbase = mask + (size_t)row0 * M_DIM + col0;
#pragma unroll
        for (int jb = 0; jb < 16; jb += 8) {
            float4 rv[8], mv[8];
#pragma unroll
            for (int j = 0; j < 8; ++j) {
                int r = wid * 16 + jb + j;
                rv[j] = *(const float4*)(rbase + (size_t)r * M_DIM + lane * 4);
                mv[j] = *(const float4*)(mbase + (size_t)r * M_DIM + lane * 4);
            }
#pragma unroll
            for (int j = 0; j < 8; ++j) {
                int r = wid * 16 + jb + j;
                const __nv_bfloat162* prow =
                    (const __nv_bfloat162*)(pred + r * PRED_PITCH);
                __nv_bfloat162 p01 = prow[lane * 2];
                __nv_bfloat162 p23 = prow[lane * 2 + 1];
                float2 f01 = __bfloat1622float2(p01);
                float2 f23 = __bfloat1622float2(p23);
                float d0 = rv[j].x - f01.x;
                float d1 = rv[j].y - f01.y;
                float d2 = rv[j].z - f23.x;
                float d3 = rv[j].w - f23.y;
                loss0 += d0 * d0 * mv[j].x;
                loss1 += d1 * d1 * mv[j].y;
                loss2 += d2 * d2 * mv[j].z;
                loss3 += d3 * d3 * mv[j].w;
            }
        }
    }
    float loss = (loss0 + loss1) + (loss2 + loss3);
#pragma unroll
    for (int o = 16; o; o >>= 1) loss += __shfl_xor_sync(0xffffffffu, loss, o);
    __shared__ float red[8];
    if (lane == 0) red[wid] = loss;
    __syncthreads();
    if (tid == 0) {
        float s = 0.f;
#pragma unroll
        for (int w = 0; w < 8; ++w) s += red[w];
        atomicAdd(&g_acc, (double)s);
        __threadfence();
        unsigned done = atomicAdd(&g_cnt, 1u);
        if (done == TOTAL_CTAS - 1) {
            // last CTA: publish result, then reset accumulators for next replay
            out[0] = (float)(*(volatile double*)&g_acc);
            *(volatile double*)&g_acc = 0.0;
            *(volatile unsigned*)&g_cnt = 0u;
        }
    }
}

extern "C" void kernel_launch(void* const* d_in, const int* in_sizes, int n_in,
                              void* d_out, int out_size) {
    const float* rating = (const float*)d_in[0];
    const float* u_mat = (const float*)d_in[1];
    const float* i_mat = (const float*)d_in[2];
    const float* mask = (const float*)d_in[3];
    float* out = (float*)d_out;

    cudaFuncSetAttribute(pmf_main, cudaFuncAttributeMaxDynamicSharedMemorySize,
                         SMEM_TOTAL);

    conv_kernel<<<(N_DIM + M_DIM) / 8, 256>>>(u_mat, i_mat);

    dim3 grid(M_DIM / BN, N_DIM / BM);  // 128 x 64 = 8192 CTAs
    pmf_main<<<grid, THREADS, SMEM_TOTAL>>>(rating, mask, out);
}